// round 2
// baseline (speedup 1.0000x reference)
#include <cuda_runtime.h>
#include <cstddef>

#define Bx   64
#define Sx   512
#define Dx   256
#define Hx   512
#define Gx   2048   // 4*H
#define OUTx 128

// ---------------- scratch (static device allocations are the allowed path) ---
__device__ float    g_xg[(size_t)Sx * Bx * Gx];   // 256 MB: gate preactivations [s][b][g]
__device__ float    g_h1[(size_t)Sx * Bx * Hx];   //  64 MB: layer-0 hidden history [s][b][j]
__device__ float    g_hT[Hx * Bx];                // current hidden, TRANSPOSED [j][b]
__device__ unsigned g_bar[2];                     // grid-barrier counters (one per scan launch)

// ---------------- init: zero barrier counters (runs every replay) ------------
__global__ void init_kernel() {
    if (threadIdx.x < 2) g_bar[threadIdx.x] = 0u;
}

// ---------------- big GEMM: C[m][n] = sum_k A[m][k]*W[n][k] + b1[n]+b2[n] -----
// M = S*B = 32768 (m -> (s,b)), N = 2048, K = 256 or 512.
// mode 0: A is x[b][s][k]  (row m0+lm -> b=lm, s=blockIdx.y)
// mode 1: A is h1[m][k] contiguous (row stride K)
__global__ void gemm_xg_kernel(const float* __restrict__ A, const float* __restrict__ W,
                               const float* __restrict__ bias1, const float* __restrict__ bias2,
                               float* __restrict__ C, int K, int mode)
{
    __shared__ float As[32][68];
    __shared__ float Bs[32][68];

    const int tid = threadIdx.x;          // 256 threads
    const int m0  = blockIdx.y * 64;
    const int n0  = blockIdx.x * 64;
    const int tx  = tid & 15;             // n quad
    const int ty  = tid >> 4;             // m quad
    const int lm  = tid >> 2;             // loader row 0..63
    const int kq0 = tid & 3;              // loader k-quad base

    const float* arow = (mode == 0)
        ? (A + (size_t)lm * (Sx * Dx) + (size_t)blockIdx.y * Dx)
        : (A + (size_t)(m0 + lm) * K);
    const float* wrow = W + (size_t)(n0 + lm) * K;

    float acc[4][4];
#pragma unroll
    for (int i = 0; i < 4; ++i)
#pragma unroll
        for (int j = 0; j < 4; ++j) acc[i][j] = 0.f;

    for (int k0 = 0; k0 < K; k0 += 32) {
        __syncthreads();
#pragma unroll
        for (int p = 0; p < 2; ++p) {
            int kq = kq0 + 4 * p;
            float4 a = *(const float4*)(arow + k0 + kq * 4);
            float4 w = *(const float4*)(wrow + k0 + kq * 4);
            As[kq*4+0][lm] = a.x; As[kq*4+1][lm] = a.y;
            As[kq*4+2][lm] = a.z; As[kq*4+3][lm] = a.w;
            Bs[kq*4+0][lm] = w.x; Bs[kq*4+1][lm] = w.y;
            Bs[kq*4+2][lm] = w.z; Bs[kq*4+3][lm] = w.w;
        }
        __syncthreads();
#pragma unroll
        for (int k = 0; k < 32; ++k) {
            float4 av = *(const float4*)&As[k][ty * 4];
            float4 bv = *(const float4*)&Bs[k][tx * 4];
            acc[0][0] += av.x * bv.x; acc[0][1] += av.x * bv.y;
            acc[0][2] += av.x * bv.z; acc[0][3] += av.x * bv.w;
            acc[1][0] += av.y * bv.x; acc[1][1] += av.y * bv.y;
            acc[1][2] += av.y * bv.z; acc[1][3] += av.y * bv.w;
            acc[2][0] += av.z * bv.x; acc[2][1] += av.z * bv.y;
            acc[2][2] += av.z * bv.z; acc[2][3] += av.z * bv.w;
            acc[3][0] += av.w * bv.x; acc[3][1] += av.w * bv.y;
            acc[3][2] += av.w * bv.z; acc[3][3] += av.w * bv.w;
        }
    }

    float4 bj;
    bj.x = bias1[n0 + tx*4 + 0] + bias2[n0 + tx*4 + 0];
    bj.y = bias1[n0 + tx*4 + 1] + bias2[n0 + tx*4 + 1];
    bj.z = bias1[n0 + tx*4 + 2] + bias2[n0 + tx*4 + 2];
    bj.w = bias1[n0 + tx*4 + 3] + bias2[n0 + tx*4 + 3];
#pragma unroll
    for (int i = 0; i < 4; ++i) {
        float4 o;
        o.x = acc[i][0] + bj.x; o.y = acc[i][1] + bj.y;
        o.z = acc[i][2] + bj.z; o.w = acc[i][3] + bj.w;
        *(float4*)(C + (size_t)(m0 + ty*4 + i) * Gx + n0 + tx*4) = o;
    }
}

// ---------------- persistent LSTM scan --------------------------------------
// grid = 128 CTAs (one per 4-hidden-unit block), block = 128 threads.
// Each CTA computes, per step, the 16 gate rows {g*H + u0 + u : g 0..3, u 0..3}
// for all 64 batches. K=512 is split across the two warp-pairs.
// Gate row local index r = g*4 + u.
#define SCAN_SMEM_FLOATS (Hx*16 + Hx*Bx + 16*68 + 16*64 + 4*64)
#define SCAN_SMEM_BYTES  (SCAN_SMEM_FLOATS * 4)

__device__ __forceinline__ float sigf(float x) { return 1.f / (1.f + __expf(-x)); }

__global__ void __launch_bounds__(128, 1) lstm_scan_kernel(
    const float* __restrict__ xg,    // [S][B][G] gate preactivations (with biases)
    const float* __restrict__ Whh,   // [G][H]
    float* __restrict__ hT,          // [H][B] current hidden (transposed)
    float* __restrict__ hist,        // [S][B][H] or nullptr
    int barIdx)
{
    extern __shared__ float smf[];
    float* Wt  = smf;                 // [512][16] transposed W tile (resident)
    float* hs  = Wt + Hx * 16;        // [512][64] h transposed
    float* gsm = hs + Hx * Bx;        // [16][68]  gates exchange
    float* psm = gsm + 16 * 68;       // [16][64]  K-split partials
    float* csm = psm + 16 * 64;       // [4][64]   cell state (persistent in smem)

    const int tid = threadIdx.x;
    const int cta = blockIdx.x;
    const int u0  = cta * 4;
    unsigned* bar = &g_bar[barIdx];
    const unsigned nctas = gridDim.x;

    // load W tile transposed: Wt[k][r], r = g*4+u -> global row g*H + u0 + u
    {
        int r  = tid & 15;
        int kc = tid >> 4;                       // 0..7 -> k range [kc*64, kc*64+64)
        int g  = r >> 2, u = r & 3;
        const float* wrow = Whh + (size_t)(g * Hx + u0 + u) * Hx;
        for (int k = kc * 64; k < kc * 64 + 64; k += 4) {
            float4 w = *(const float4*)(wrow + k);
            Wt[(k+0)*16 + r] = w.x;
            Wt[(k+1)*16 + r] = w.y;
            Wt[(k+2)*16 + r] = w.z;
            Wt[(k+3)*16 + r] = w.w;
        }
    }
    for (int i = tid; i < 4 * 64; i += 128) csm[i] = 0.f;
    __syncthreads();

    const int half = tid >> 6;      // K-split half
    const int lt   = tid & 63;
    const int bq   = lt & 15;       // batch quad
    const int rq   = lt >> 4;       // gate index (rows rq*4 .. rq*4+3)
    const int b0   = bq * 4;

    for (int s = 0; s < Sx; ++s) {
        float acc[4][4];
#pragma unroll
        for (int i = 0; i < 4; ++i)
#pragma unroll
            for (int j = 0; j < 4; ++j) acc[i][j] = 0.f;

        if (s > 0) {
            // reload h (written by other SMs last step) -> smem, L2 path
            const float4* src = (const float4*)hT;
            float4*       dst = (float4*)hs;
#pragma unroll 8
            for (int i = 0; i < 64; ++i)
                dst[tid + i * 128] = __ldcg(src + tid + i * 128);
            __syncthreads();

            const float* hp = hs + (size_t)(half * 256) * 64 + b0;
            const float* wp = Wt + (size_t)(half * 256) * 16 + rq * 4;
#pragma unroll 4
            for (int k = 0; k < 256; ++k) {
                float4 hv = *(const float4*)(hp + k * 64);
                float4 wv = *(const float4*)(wp + k * 16);
                acc[0][0] += hv.x * wv.x; acc[0][1] += hv.x * wv.y;
                acc[0][2] += hv.x * wv.z; acc[0][3] += hv.x * wv.w;
                acc[1][0] += hv.y * wv.x; acc[1][1] += hv.y * wv.y;
                acc[1][2] += hv.y * wv.z; acc[1][3] += hv.y * wv.w;
                acc[2][0] += hv.z * wv.x; acc[2][1] += hv.z * wv.y;
                acc[2][2] += hv.z * wv.z; acc[2][3] += hv.z * wv.w;
                acc[3][0] += hv.w * wv.x; acc[3][1] += hv.w * wv.y;
                acc[3][2] += hv.w * wv.z; acc[3][3] += hv.w * wv.w;
            }
        }
        __syncthreads();
        if (half == 1) {
#pragma unroll
            for (int j = 0; j < 4; ++j) {
                float4 v = make_float4(acc[0][j], acc[1][j], acc[2][j], acc[3][j]);
                *(float4*)&psm[(rq * 4 + j) * 64 + b0] = v;
            }
        }
        __syncthreads();
        if (half == 0) {
#pragma unroll
            for (int i = 0; i < 4; ++i) {
                float4 xv = *(const float4*)(xg + (size_t)(s * Bx + b0 + i) * Gx + rq * Hx + u0);
                acc[i][0] += xv.x; acc[i][1] += xv.y;
                acc[i][2] += xv.z; acc[i][3] += xv.w;
            }
#pragma unroll
            for (int j = 0; j < 4; ++j) {
                float4 p = *(const float4*)&psm[(rq * 4 + j) * 64 + b0];
                float4 v = make_float4(acc[0][j] + p.x, acc[1][j] + p.y,
                                       acc[2][j] + p.z, acc[3][j] + p.w);
                *(float4*)&gsm[(rq * 4 + j) * 68 + b0] = v;
            }
        }
        __syncthreads();
        if (tid < 64) {
            int uu = tid >> 4;
            int bb = (tid & 15) * 4;
            float4 iv = *(const float4*)&gsm[( 0 + uu) * 68 + bb];
            float4 fv = *(const float4*)&gsm[( 4 + uu) * 68 + bb];
            float4 gv = *(const float4*)&gsm[( 8 + uu) * 68 + bb];
            float4 ov = *(const float4*)&gsm[(12 + uu) * 68 + bb];
            float4 cv = *(float4*)&csm[uu * 64 + bb];
            float4 hv4;
#define LSTM_ELEM(X) { \
            float ci = sigf(iv.X); float cf = sigf(fv.X); \
            float cg = tanhf(gv.X); float co = sigf(ov.X); \
            cv.X = cf * cv.X + ci * cg; \
            hv4.X = co * tanhf(cv.X); }
            LSTM_ELEM(x) LSTM_ELEM(y) LSTM_ELEM(z) LSTM_ELEM(w)
#undef LSTM_ELEM
            *(float4*)&csm[uu * 64 + bb] = cv;
            *(float4*)(hT + (size_t)(u0 + uu) * Bx + bb) = hv4;
            if (hist) {
                int j = u0 + uu;
                hist[(size_t)(s * Bx + bb + 0) * Hx + j] = hv4.x;
                hist[(size_t)(s * Bx + bb + 1) * Hx + j] = hv4.y;
                hist[(size_t)(s * Bx + bb + 2) * Hx + j] = hv4.z;
                hist[(size_t)(s * Bx + bb + 3) * Hx + j] = hv4.w;
            }
        }
        // ---- grid barrier ----
        __syncthreads();
        if (tid == 0) {
            __threadfence();
            atomicAdd(bar, 1u);
            unsigned target = nctas * (unsigned)(s + 1);
            while (*((volatile unsigned*)bar) < target) {}
            __threadfence();
        }
        __syncthreads();
    }
}

// ---------------- final FC ---------------------------------------------------
__global__ void fc_kernel(const float* __restrict__ hT, const float* __restrict__ fw,
                          const float* __restrict__ fb, float* __restrict__ out)
{
    __shared__ float hb[Hx];
    int b = blockIdx.x;
    int o = threadIdx.x;          // 128 threads
    for (int j = threadIdx.x; j < Hx; j += OUTx) hb[j] = hT[j * Bx + b];
    __syncthreads();
    float acc = fb[o];
    const float* wr = fw + (size_t)o * Hx;
#pragma unroll 4
    for (int j = 0; j < Hx; j += 4) {
        float4 w = *(const float4*)(wr + j);
        float4 h = *(const float4*)(hb + j);
        acc += w.x * h.x + w.y * h.y + w.z * h.z + w.w * h.w;
    }
    out[b * OUTx + o] = acc;
}

// ---------------- launch ------------------------------------------------------
extern "C" void kernel_launch(void* const* d_in, const int* in_sizes, int n_in,
                              void* d_out, int out_size)
{
    const float* x    = (const float*)d_in[0];
    const float* Wih0 = (const float*)d_in[1];
    const float* Whh0 = (const float*)d_in[2];
    const float* bih0 = (const float*)d_in[3];
    const float* bhh0 = (const float*)d_in[4];
    const float* Wih1 = (const float*)d_in[5];
    const float* Whh1 = (const float*)d_in[6];
    const float* bih1 = (const float*)d_in[7];
    const float* bhh1 = (const float*)d_in[8];
    const float* fcw  = (const float*)d_in[9];
    const float* fcb  = (const float*)d_in[10];
    float* out = (float*)d_out;

    cudaFuncSetAttribute((const void*)lstm_scan_kernel,
                         cudaFuncAttributeMaxDynamicSharedMemorySize, SCAN_SMEM_BYTES);

    void *xg_p, *h1_p, *hT_p;
    cudaGetSymbolAddress(&xg_p, g_xg);
    cudaGetSymbolAddress(&h1_p, g_h1);
    cudaGetSymbolAddress(&hT_p, g_hT);

    init_kernel<<<1, 32>>>();

    dim3 ggrid(Gx / 64, (Sx * Bx) / 64);   // (32, 512)
    // layer 0 input GEMM: xg0 = x @ W_ih0^T + (b_ih0 + b_hh0)
    gemm_xg_kernel<<<ggrid, 256>>>(x, Wih0, bih0, bhh0, (float*)xg_p, Dx, 0);
    // layer 0 scan (writes full h history)
    lstm_scan_kernel<<<128, 128, SCAN_SMEM_BYTES>>>((const float*)xg_p, Whh0,
                                                    (float*)hT_p, (float*)h1_p, 0);
    // layer 1 input GEMM: xg1 = h1 @ W_ih1^T + (b_ih1 + b_hh1)
    gemm_xg_kernel<<<ggrid, 256>>>((const float*)h1_p, Wih1, bih1, bhh1,
                                   (float*)xg_p, Hx, 1);
    // layer 1 scan (only final h needed)
    lstm_scan_kernel<<<128, 128, SCAN_SMEM_BYTES>>>((const float*)xg_p, Whh1,
                                                    (float*)hT_p, nullptr, 1);
    // final FC on last hidden state
    fc_kernel<<<Bx, OUTx>>>((const float*)hT_p, fcw, fcb, out);
}